// round 16
// baseline (speedup 1.0000x reference)
#include <cuda_runtime.h>
#include <cuda_bf16.h>
#include <cuda_fp16.h>
#include <cstdint>
#include <cstring>

// GCNConv: out = D_in^{-1/2} * A * (D_out^{-1/2} * (X @ W)) + bias
// Stage 0: bake W -> fp16 frag layout, kstep-paired uint4 (R11, verbatim)
// Stage 1: R11 GEMM (verbatim): 128 rows/256 thr, B-frags L1-resident
// Stage 2: aggregate: 2 rows per LDG.128 (half-warp split) + shfl reduce

#define MAX_N 100000

__device__ __half g_h[(size_t)MAX_N * 128];
// frag layout: [ntile 0..15][spair 0..3][lane 0..31] =
//   {even-kstep fh0, even fh1, odd fh0, odd fh1}
__device__ uint4  g_wfrag[16 * 4 * 32];

// ---------------------------------------------------------------------------
// helpers
// ---------------------------------------------------------------------------
__device__ __forceinline__ unsigned h2u(__half2 v) {
    unsigned r;
    memcpy(&r, &v, 4);
    return r;
}

__device__ __forceinline__ unsigned cvt_f16x2(float2 v) {
    unsigned r;
    asm("cvt.rn.f16x2.f32 %0, %1, %2;" : "=r"(r) : "f"(v.y), "f"(v.x));
    return r;
}

__device__ __forceinline__ void mma_f16(float* c, const unsigned* a,
                                        unsigned b0, unsigned b1) {
    asm volatile(
        "mma.sync.aligned.m16n8k16.row.col.f32.f16.f16.f32 "
        "{%0,%1,%2,%3}, {%4,%5,%6,%7}, {%8,%9}, {%0,%1,%2,%3};"
        : "+f"(c[0]), "+f"(c[1]), "+f"(c[2]), "+f"(c[3])
        : "r"(a[0]), "r"(a[1]), "r"(a[2]), "r"(a[3]), "r"(b0), "r"(b1));
}

// ---------------------------------------------------------------------------
// Stage 0: bake W [k][n] fp32 into kstep-paired fp16 frag layout. (R11)
// ---------------------------------------------------------------------------
__global__ __launch_bounds__(256) void wfrag_kernel(const float* __restrict__ w) {
    int idx = blockIdx.x * 256 + threadIdx.x;   // 0..2047
    int lane = idx & 31;
    int sp   = (idx >> 5) & 3;
    int ntile = idx >> 7;
    int lg = lane >> 2;
    int lt = lane & 3;
    int nn = ntile * 8 + lg;
    int k0 = (2 * sp) * 16 + 2 * lt;

    float e00 = w[(k0    ) * 128 + nn];
    float e01 = w[(k0 + 1) * 128 + nn];
    float e10 = w[(k0 + 8) * 128 + nn];
    float e11 = w[(k0 + 9) * 128 + nn];
    float o00 = w[(k0 + 16) * 128 + nn];
    float o01 = w[(k0 + 17) * 128 + nn];
    float o10 = w[(k0 + 24) * 128 + nn];
    float o11 = w[(k0 + 25) * 128 + nn];

    g_wfrag[idx] = make_uint4(h2u(__floats2half2_rn(e00, e01)),
                              h2u(__floats2half2_rn(e10, e11)),
                              h2u(__floats2half2_rn(o00, o01)),
                              h2u(__floats2half2_rn(o10, o11)));
}

// ---------------------------------------------------------------------------
// Stage 1 GEMM (R11 verbatim): block = 128 rows, 8 warps; warp owns rows
// [wid*16, wid*16+16) x cols [0,128) = 16 n8-tiles.
// ---------------------------------------------------------------------------
__global__ __launch_bounds__(256, 2) void gemm_mma_kernel(
    const float* __restrict__ x,       // [n,128]
    const uint4* __restrict__ wfrag,   // baked W frags (paired)
    const int*   __restrict__ colptr,  // [n+1]
    __half*      __restrict__ h,       // [n,128]
    int n)
{
    const int tid  = threadIdx.x;
    const int wid  = tid >> 5;
    const int lane = tid & 31;
    const int lg   = lane >> 2;
    const int lt   = lane & 3;
    const int rowbase = blockIdx.x * 128 + wid * 16;

    const int r0 = rowbase + lg;       // rows r0, r0+8
    const int r1 = r0 + 8;
    const bool v0 = r0 < n, v1 = r1 < n;

    const float2* xr0 = reinterpret_cast<const float2*>(x + (size_t)r0 * 128);
    const float2* xr1 = reinterpret_cast<const float2*>(x + (size_t)r1 * 128);

    float acc[16][4];
    #pragma unroll
    for (int nt = 0; nt < 16; nt++)
        #pragma unroll
        for (int j = 0; j < 4; j++)
            acc[nt][j] = 0.f;

    const float2 z2 = make_float2(0.f, 0.f);

    float2 pe[4], po[4];
    {
        const int kq = lt;
        pe[0] = v0 ? xr0[kq]      : z2;
        pe[1] = v1 ? xr1[kq]      : z2;
        pe[2] = v0 ? xr0[kq + 4]  : z2;
        pe[3] = v1 ? xr1[kq + 4]  : z2;
        po[0] = v0 ? xr0[kq + 8]  : z2;
        po[1] = v1 ? xr1[kq + 8]  : z2;
        po[2] = v0 ? xr0[kq + 12] : z2;
        po[3] = v1 ? xr1[kq + 12] : z2;
    }

    const uint4* wf = wfrag + lane;

    #pragma unroll
    for (int sp = 0; sp < 4; sp++) {
        unsigned ae[4], ao[4];
        #pragma unroll
        for (int j = 0; j < 4; j++) {
            ae[j] = cvt_f16x2(pe[j]);
            ao[j] = cvt_f16x2(po[j]);
        }

        if (sp < 3) {
            const int kq = (2 * sp + 2) * 8 + lt;
            pe[0] = v0 ? xr0[kq]      : z2;
            pe[1] = v1 ? xr1[kq]      : z2;
            pe[2] = v0 ? xr0[kq + 4]  : z2;
            pe[3] = v1 ? xr1[kq + 4]  : z2;
            po[0] = v0 ? xr0[kq + 8]  : z2;
            po[1] = v1 ? xr1[kq + 8]  : z2;
            po[2] = v0 ? xr0[kq + 12] : z2;
            po[3] = v1 ? xr1[kq + 12] : z2;
        }

        #pragma unroll
        for (int nt = 0; nt < 16; nt++) {
            uint4 b = wf[(nt * 4 + sp) * 32];
            mma_f16(acc[nt], ae, b.x, b.y);
            mma_f16(acc[nt], ao, b.z, b.w);
        }
    }

    float s0 = 0.f, s1 = 0.f;
    if (v0) {
        float d = (float)(colptr[r0 + 1] - colptr[r0]);
        s0 = (d > 0.f) ? rsqrtf(d) : 0.f;
    }
    if (v1) {
        float d = (float)(colptr[r1 + 1] - colptr[r1]);
        s1 = (d > 0.f) ? rsqrtf(d) : 0.f;
    }

    #pragma unroll
    for (int nt = 0; nt < 16; nt++) {
        const int col = nt * 8 + 2 * lt;
        if (v0) {
            __half2 p = __floats2half2_rn(acc[nt][0] * s0, acc[nt][1] * s0);
            *reinterpret_cast<unsigned*>(&h[(size_t)r0 * 128 + col]) = h2u(p);
        }
        if (v1) {
            __half2 p = __floats2half2_rn(acc[nt][2] * s1, acc[nt][3] * s1);
            *reinterpret_cast<unsigned*>(&h[(size_t)r1 * 128 + col]) = h2u(p);
        }
    }
}

// ---------------------------------------------------------------------------
// Stage 2: aggregation. 8 nodes/block, warp per node.
// Fast path (deg==16, aligned): 8 LDG.128 gathers — lanes 0..15 fetch edge 2p,
// lanes 16..31 fetch edge 2p+1, 16B per lane. Half-warp shfl reduce at end;
// lanes 0..15 store the 512B output row.
// ---------------------------------------------------------------------------
__global__ __launch_bounds__(256) void aggregate_kernel(
    const __half* __restrict__ h,
    const int*    __restrict__ rowptr,
    const int*    __restrict__ colind,
    const float*  __restrict__ bias,
    float*        __restrict__ out,
    int n)
{
    const int node = blockIdx.x * 8 + (threadIdx.x >> 5);
    const int lane = threadIdx.x & 31;
    if (node >= n) return;

    const int beg = rowptr[node];
    const int end = rowptr[node + 1];

    if (end - beg == 16 && (beg & 3) == 0) {
        const int4* cp = reinterpret_cast<const int4*>(colind + beg);
        int4 c0 = __ldg(cp + 0);
        int4 c1 = __ldg(cp + 1);
        int4 c2 = __ldg(cp + 2);
        int4 c3 = __ldg(cp + 3);
        int idx[16] = {c0.x, c0.y, c0.z, c0.w, c1.x, c1.y, c1.z, c1.w,
                       c2.x, c2.y, c2.z, c2.w, c3.x, c3.y, c3.z, c3.w};

        const uint4* h4 = reinterpret_cast<const uint4*>(h);  // 16B = 8 halfs
        const int half_sel = lane >> 4;     // 0: even edges, 1: odd edges
        const int hl = lane & 15;           // uint4 column within row (0..15)

        // issue all 8 paired gathers
        uint4 v[8];
        #pragma unroll
        for (int p = 0; p < 8; p++) {
            int row = idx[2 * p + half_sel];
            v[p] = h4[(size_t)row * 16 + hl];
        }

        // accumulate 8 halfs -> 8 floats
        float a[8] = {0.f, 0.f, 0.f, 0.f, 0.f, 0.f, 0.f, 0.f};
        #pragma unroll
        for (int p = 0; p < 8; p++) {
            float2 f;
            f = __half22float2(*reinterpret_cast<__half2*>(&v[p].x));
            a[0] += f.x; a[1] += f.y;
            f = __half22float2(*reinterpret_cast<__half2*>(&v[p].y));
            a[2] += f.x; a[3] += f.y;
            f = __half22float2(*reinterpret_cast<__half2*>(&v[p].z));
            a[4] += f.x; a[5] += f.y;
            f = __half22float2(*reinterpret_cast<__half2*>(&v[p].w));
            a[6] += f.x; a[7] += f.y;
        }

        // fold odd-edge half-warp into even-edge half-warp
        #pragma unroll
        for (int j = 0; j < 8; j++) {
            float other = __shfl_down_sync(0xFFFFFFFFu, a[j], 16);
            a[j] += other;
        }

        if (half_sel == 0) {
            const float s = 0.25f;              // 1/sqrt(16)
            const float4* b4 = reinterpret_cast<const float4*>(bias);
            float4 b0 = b4[hl * 2];
            float4 b1 = b4[hl * 2 + 1];
            float4 o0 = make_float4(a[0] * s + b0.x, a[1] * s + b0.y,
                                    a[2] * s + b0.z, a[3] * s + b0.w);
            float4 o1 = make_float4(a[4] * s + b1.x, a[5] * s + b1.y,
                                    a[6] * s + b1.z, a[7] * s + b1.w);
            float4* op = reinterpret_cast<float4*>(out + (size_t)node * 128 + hl * 8);
            op[0] = o0;
            op[1] = o1;
        }
        return;
    }

    // ---- general path (any degree) ----
    const uint2* h2 = reinterpret_cast<const uint2*>(h);
    float4 a0 = make_float4(0.f, 0.f, 0.f, 0.f);
    for (int e = beg; e < end; e++) {
        int i0 = __ldg(&colind[e]);
        uint2 u0 = h2[(size_t)i0 * 32 + lane];
        float2 f;
        f = __half22float2(*reinterpret_cast<__half2*>(&u0.x));
        a0.x += f.x; a0.y += f.y;
        f = __half22float2(*reinterpret_cast<__half2*>(&u0.y));
        a0.z += f.x; a0.w += f.y;
    }

    float deg = (float)(end - beg);
    float s = (deg > 0.f) ? rsqrtf(deg) : 0.f;

    float4 b = reinterpret_cast<const float4*>(bias)[lane];
    float4 o;
    o.x = a0.x * s + b.x;
    o.y = a0.y * s + b.y;
    o.z = a0.z * s + b.z;
    o.w = a0.w * s + b.w;

    reinterpret_cast<float4*>(out)[(size_t)node * 32 + lane] = o;
}

// ---------------------------------------------------------------------------
// launch
// ---------------------------------------------------------------------------
extern "C" void kernel_launch(void* const* d_in, const int* in_sizes, int n_in,
                              void* d_out, int out_size)
{
    const float* x      = (const float*)d_in[0];
    const float* weight = (const float*)d_in[1];
    const float* bias   = (const float*)d_in[2];
    const int*   rowptr = (const int*)  d_in[3];
    const int*   colind = (const int*)  d_in[4];
    const int*   colptr = (const int*)  d_in[5];

    const int n = in_sizes[3] - 1;
    float* out = (float*)d_out;

    __half* h_scratch = nullptr;
    cudaGetSymbolAddress((void**)&h_scratch, g_h);
    uint4* wfrag = nullptr;
    cudaGetSymbolAddress((void**)&wfrag, g_wfrag);

    // Stage 0: bake W frags (2048 uint4)
    wfrag_kernel<<<8, 256>>>(weight);

    // Stage 1: GEMM (128 rows per block, 256 threads) — R11
    int gemm_blocks = (n + 127) / 128;
    gemm_mma_kernel<<<gemm_blocks, 256>>>(x, wfrag, colptr, h_scratch, n);

    // Stage 2: aggregate
    int agg_blocks = (n + 7) / 8;
    aggregate_kernel<<<agg_blocks, 256>>>(h_scratch, rowptr, colind, bias,
                                          out, n);
}

// round 17
// speedup vs baseline: 1.1904x; 1.1904x over previous
#include <cuda_runtime.h>
#include <cuda_bf16.h>
#include <cuda_fp16.h>
#include <cstdint>
#include <cstring>

// GCNConv: out = D_in^{-1/2} * A * (D_out^{-1/2} * (X @ W)) + bias
// Stage 0: bake W -> fp16 frag layout, kstep-paired uint4 (R11, verbatim)
// Stage 1: R11 GEMM (verbatim): 128 rows/256 thr, B-frags L1-resident
// Stage 2: aggregate: paired gather (2 rows / LDG.128) with register-only
//          index selection (fixes R16's local-memory spill)

#define MAX_N 100000

__device__ __half g_h[(size_t)MAX_N * 128];
// frag layout: [ntile 0..15][spair 0..3][lane 0..31] =
//   {even-kstep fh0, even fh1, odd fh0, odd fh1}
__device__ uint4  g_wfrag[16 * 4 * 32];

// ---------------------------------------------------------------------------
// helpers
// ---------------------------------------------------------------------------
__device__ __forceinline__ unsigned h2u(__half2 v) {
    unsigned r;
    memcpy(&r, &v, 4);
    return r;
}

__device__ __forceinline__ unsigned cvt_f16x2(float2 v) {
    unsigned r;
    asm("cvt.rn.f16x2.f32 %0, %1, %2;" : "=r"(r) : "f"(v.y), "f"(v.x));
    return r;
}

__device__ __forceinline__ void mma_f16(float* c, const unsigned* a,
                                        unsigned b0, unsigned b1) {
    asm volatile(
        "mma.sync.aligned.m16n8k16.row.col.f32.f16.f16.f32 "
        "{%0,%1,%2,%3}, {%4,%5,%6,%7}, {%8,%9}, {%0,%1,%2,%3};"
        : "+f"(c[0]), "+f"(c[1]), "+f"(c[2]), "+f"(c[3])
        : "r"(a[0]), "r"(a[1]), "r"(a[2]), "r"(a[3]), "r"(b0), "r"(b1));
}

// ---------------------------------------------------------------------------
// Stage 0: bake W [k][n] fp32 into kstep-paired fp16 frag layout. (R11)
// ---------------------------------------------------------------------------
__global__ __launch_bounds__(256) void wfrag_kernel(const float* __restrict__ w) {
    int idx = blockIdx.x * 256 + threadIdx.x;   // 0..2047
    int lane = idx & 31;
    int sp   = (idx >> 5) & 3;
    int ntile = idx >> 7;
    int lg = lane >> 2;
    int lt = lane & 3;
    int nn = ntile * 8 + lg;
    int k0 = (2 * sp) * 16 + 2 * lt;

    float e00 = w[(k0    ) * 128 + nn];
    float e01 = w[(k0 + 1) * 128 + nn];
    float e10 = w[(k0 + 8) * 128 + nn];
    float e11 = w[(k0 + 9) * 128 + nn];
    float o00 = w[(k0 + 16) * 128 + nn];
    float o01 = w[(k0 + 17) * 128 + nn];
    float o10 = w[(k0 + 24) * 128 + nn];
    float o11 = w[(k0 + 25) * 128 + nn];

    g_wfrag[idx] = make_uint4(h2u(__floats2half2_rn(e00, e01)),
                              h2u(__floats2half2_rn(e10, e11)),
                              h2u(__floats2half2_rn(o00, o01)),
                              h2u(__floats2half2_rn(o10, o11)));
}

// ---------------------------------------------------------------------------
// Stage 1 GEMM (R11 verbatim): block = 128 rows, 8 warps; warp owns rows
// [wid*16, wid*16+16) x cols [0,128) = 16 n8-tiles.
// ---------------------------------------------------------------------------
__global__ __launch_bounds__(256, 2) void gemm_mma_kernel(
    const float* __restrict__ x,       // [n,128]
    const uint4* __restrict__ wfrag,   // baked W frags (paired)
    const int*   __restrict__ colptr,  // [n+1]
    __half*      __restrict__ h,       // [n,128]
    int n)
{
    const int tid  = threadIdx.x;
    const int wid  = tid >> 5;
    const int lane = tid & 31;
    const int lg   = lane >> 2;
    const int lt   = lane & 3;
    const int rowbase = blockIdx.x * 128 + wid * 16;

    const int r0 = rowbase + lg;       // rows r0, r0+8
    const int r1 = r0 + 8;
    const bool v0 = r0 < n, v1 = r1 < n;

    const float2* xr0 = reinterpret_cast<const float2*>(x + (size_t)r0 * 128);
    const float2* xr1 = reinterpret_cast<const float2*>(x + (size_t)r1 * 128);

    float acc[16][4];
    #pragma unroll
    for (int nt = 0; nt < 16; nt++)
        #pragma unroll
        for (int j = 0; j < 4; j++)
            acc[nt][j] = 0.f;

    const float2 z2 = make_float2(0.f, 0.f);

    float2 pe[4], po[4];
    {
        const int kq = lt;
        pe[0] = v0 ? xr0[kq]      : z2;
        pe[1] = v1 ? xr1[kq]      : z2;
        pe[2] = v0 ? xr0[kq + 4]  : z2;
        pe[3] = v1 ? xr1[kq + 4]  : z2;
        po[0] = v0 ? xr0[kq + 8]  : z2;
        po[1] = v1 ? xr1[kq + 8]  : z2;
        po[2] = v0 ? xr0[kq + 12] : z2;
        po[3] = v1 ? xr1[kq + 12] : z2;
    }

    const uint4* wf = wfrag + lane;

    #pragma unroll
    for (int sp = 0; sp < 4; sp++) {
        unsigned ae[4], ao[4];
        #pragma unroll
        for (int j = 0; j < 4; j++) {
            ae[j] = cvt_f16x2(pe[j]);
            ao[j] = cvt_f16x2(po[j]);
        }

        if (sp < 3) {
            const int kq = (2 * sp + 2) * 8 + lt;
            pe[0] = v0 ? xr0[kq]      : z2;
            pe[1] = v1 ? xr1[kq]      : z2;
            pe[2] = v0 ? xr0[kq + 4]  : z2;
            pe[3] = v1 ? xr1[kq + 4]  : z2;
            po[0] = v0 ? xr0[kq + 8]  : z2;
            po[1] = v1 ? xr1[kq + 8]  : z2;
            po[2] = v0 ? xr0[kq + 12] : z2;
            po[3] = v1 ? xr1[kq + 12] : z2;
        }

        #pragma unroll
        for (int nt = 0; nt < 16; nt++) {
            uint4 b = wf[(nt * 4 + sp) * 32];
            mma_f16(acc[nt], ae, b.x, b.y);
            mma_f16(acc[nt], ao, b.z, b.w);
        }
    }

    float s0 = 0.f, s1 = 0.f;
    if (v0) {
        float d = (float)(colptr[r0 + 1] - colptr[r0]);
        s0 = (d > 0.f) ? rsqrtf(d) : 0.f;
    }
    if (v1) {
        float d = (float)(colptr[r1 + 1] - colptr[r1]);
        s1 = (d > 0.f) ? rsqrtf(d) : 0.f;
    }

    #pragma unroll
    for (int nt = 0; nt < 16; nt++) {
        const int col = nt * 8 + 2 * lt;
        if (v0) {
            __half2 p = __floats2half2_rn(acc[nt][0] * s0, acc[nt][1] * s0);
            *reinterpret_cast<unsigned*>(&h[(size_t)r0 * 128 + col]) = h2u(p);
        }
        if (v1) {
            __half2 p = __floats2half2_rn(acc[nt][2] * s1, acc[nt][3] * s1);
            *reinterpret_cast<unsigned*>(&h[(size_t)r1 * 128 + col]) = h2u(p);
        }
    }
}

// ---------------------------------------------------------------------------
// Stage 2: aggregation. 8 nodes/block, warp per node.
// Fast path (deg==16, aligned): lanes 0..15 gather even edges' rows,
// lanes 16..31 gather odd edges' rows, 16B/lane -> 8 LDG.128 per node.
// Index selection is register-only (constant-indexed arrays + SEL).
// ---------------------------------------------------------------------------
__global__ __launch_bounds__(256) void aggregate_kernel(
    const __half* __restrict__ h,
    const int*    __restrict__ rowptr,
    const int*    __restrict__ colind,
    const float*  __restrict__ bias,
    float*        __restrict__ out,
    int n)
{
    const int node = blockIdx.x * 8 + (threadIdx.x >> 5);
    const int lane = threadIdx.x & 31;
    if (node >= n) return;

    const int beg = rowptr[node];
    const int end = rowptr[node + 1];

    if (end - beg == 16 && (beg & 3) == 0) {
        const int4* cp = reinterpret_cast<const int4*>(colind + beg);
        int4 c0 = __ldg(cp + 0);
        int4 c1 = __ldg(cp + 1);
        int4 c2 = __ldg(cp + 2);
        int4 c3 = __ldg(cp + 3);
        // constant-indexed arrays (stay in registers)
        int even[8] = {c0.x, c0.z, c1.x, c1.z, c2.x, c2.z, c3.x, c3.z};
        int odd[8]  = {c0.y, c0.w, c1.y, c1.w, c2.y, c2.w, c3.y, c3.w};

        const uint4* h4 = reinterpret_cast<const uint4*>(h);  // 16B = 8 halfs
        const bool is_odd_half = (lane >> 4) != 0;
        const int hl = lane & 15;           // uint4 column within row (0..15)

        // issue all 8 paired gathers (row select = SEL, no local memory)
        uint4 v[8];
        #pragma unroll
        for (int p = 0; p < 8; p++) {
            int row = is_odd_half ? odd[p] : even[p];
            v[p] = h4[(size_t)row * 16 + hl];
        }

        // accumulate 8 halfs -> 8 floats
        float a[8] = {0.f, 0.f, 0.f, 0.f, 0.f, 0.f, 0.f, 0.f};
        #pragma unroll
        for (int p = 0; p < 8; p++) {
            float2 f;
            f = __half22float2(*reinterpret_cast<__half2*>(&v[p].x));
            a[0] += f.x; a[1] += f.y;
            f = __half22float2(*reinterpret_cast<__half2*>(&v[p].y));
            a[2] += f.x; a[3] += f.y;
            f = __half22float2(*reinterpret_cast<__half2*>(&v[p].z));
            a[4] += f.x; a[5] += f.y;
            f = __half22float2(*reinterpret_cast<__half2*>(&v[p].w));
            a[6] += f.x; a[7] += f.y;
        }

        // fold odd-edge half-warp into even-edge half-warp
        #pragma unroll
        for (int j = 0; j < 8; j++) {
            float other = __shfl_down_sync(0xFFFFFFFFu, a[j], 16);
            a[j] += other;
        }

        if (!is_odd_half) {
            const float s = 0.25f;              // 1/sqrt(16)
            const float4* b4 = reinterpret_cast<const float4*>(bias);
            float4 b0 = b4[hl * 2];
            float4 b1 = b4[hl * 2 + 1];
            float4 o0 = make_float4(a[0] * s + b0.x, a[1] * s + b0.y,
                                    a[2] * s + b0.z, a[3] * s + b0.w);
            float4 o1 = make_float4(a[4] * s + b1.x, a[5] * s + b1.y,
                                    a[6] * s + b1.z, a[7] * s + b1.w);
            float4* op = reinterpret_cast<float4*>(out + (size_t)node * 128 + hl * 8);
            op[0] = o0;
            op[1] = o1;
        }
        return;
    }

    // ---- general path (any degree) ----
    const uint2* h2 = reinterpret_cast<const uint2*>(h);
    float4 a0 = make_float4(0.f, 0.f, 0.f, 0.f);
    for (int e = beg; e < end; e++) {
        int i0 = __ldg(&colind[e]);
        uint2 u0 = h2[(size_t)i0 * 32 + lane];
        float2 f;
        f = __half22float2(*reinterpret_cast<__half2*>(&u0.x));
        a0.x += f.x; a0.y += f.y;
        f = __half22float2(*reinterpret_cast<__half2*>(&u0.y));
        a0.z += f.x; a0.w += f.y;
    }

    float deg = (float)(end - beg);
    float s = (deg > 0.f) ? rsqrtf(deg) : 0.f;

    float4 b = reinterpret_cast<const float4*>(bias)[lane];
    float4 o;
    o.x = a0.x * s + b.x;
    o.y = a0.y * s + b.y;
    o.z = a0.z * s + b.z;
    o.w = a0.w * s + b.w;

    reinterpret_cast<float4*>(out)[(size_t)node * 32 + lane] = o;
}

// ---------------------------------------------------------------------------
// launch
// ---------------------------------------------------------------------------
extern "C" void kernel_launch(void* const* d_in, const int* in_sizes, int n_in,
                              void* d_out, int out_size)
{
    const float* x      = (const float*)d_in[0];
    const float* weight = (const float*)d_in[1];
    const float* bias   = (const float*)d_in[2];
    const int*   rowptr = (const int*)  d_in[3];
    const int*   colind = (const int*)  d_in[4];
    const int*   colptr = (const int*)  d_in[5];

    const int n = in_sizes[3] - 1;
    float* out = (float*)d_out;

    __half* h_scratch = nullptr;
    cudaGetSymbolAddress((void**)&h_scratch, g_h);
    uint4* wfrag = nullptr;
    cudaGetSymbolAddress((void**)&wfrag, g_wfrag);

    // Stage 0: bake W frags (2048 uint4)
    wfrag_kernel<<<8, 256>>>(weight);

    // Stage 1: GEMM (128 rows per block, 256 threads) — R11
    int gemm_blocks = (n + 127) / 128;
    gemm_mma_kernel<<<gemm_blocks, 256>>>(x, wfrag, colptr, h_scratch, n);

    // Stage 2: aggregate
    int agg_blocks = (n + 7) / 8;
    aggregate_kernel<<<agg_blocks, 256>>>(h_scratch, rowptr, colind, bias,
                                          out, n);
}